// round 10
// baseline (speedup 1.0000x reference)
#include <cuda_runtime.h>

#define HIDDEN 32
#define FF 40
#define TSTEPS 512
#define BATCH 16384
#define EPB 128           /* elements per block; each thread handles 4 */
#define THREADS 256       /* 8 warps = 2 roles x 4 column groups */

typedef unsigned long long u64;

__device__ __forceinline__ u64 pk(float a, float b) {
    u64 r; asm("mov.b64 %0,{%1,%2};" : "=l"(r) : "f"(a), "f"(b)); return r;
}
__device__ __forceinline__ void upk(u64 v, float& a, float& b) {
    asm("mov.b64 {%0,%1},%2;" : "=f"(a), "=f"(b) : "l"(v));
}
__device__ __forceinline__ u64 f2fma(u64 a, u64 b, u64 c) {
    u64 d; asm("fma.rn.f32x2 %0,%1,%2,%3;" : "=l"(d) : "l"(a), "l"(b), "l"(c)); return d;
}
// sigmoid via ex2/rcp approx (~1e-6 rel; proven rel_err ~2.5e-7 across rounds)
__device__ __forceinline__ float sigm(float x) {
    float e, r;
    asm("ex2.approx.ftz.f32 %0,%1;" : "=f"(e) : "f"(x * -1.4426950408889634f));
    asm("rcp.approx.ftz.f32 %0,%1;" : "=f"(r) : "f"(1.0f + e));
    return r;
}

// Dynamic-smem layout (bytes; all u64 regions 8B-aligned)
#define OFF_W1HH 0            /* 33*40 f = 5280  */
#define OFF_W1HO 5280
#define OFF_W2HH 10560        /* 40*32 f = 5120  */
#define OFF_W2HO 15680        /* 40 f            */
#define OFF_B1HH 15840
#define OFF_B1HO 16000
#define OFF_B2HH 16160        /* 32 f -> 16288   */
#define OFF_HBUF 16288        /* u64[16*EPB] = 16384 */
#define OFF_SST  32672        /* u64[20*EPB] = 20480 */
#define OFF_OBUF 53152        /* f[3*EPB] = 1536 */
#define SMEM_TOTAL 54688

__global__ void __launch_bounds__(THREADS, 1) rnn_e4_kernel(
    const float* __restrict__ inp,
    const float* __restrict__ W1hh, const float* __restrict__ b1hh,
    const float* __restrict__ W2hh, const float* __restrict__ b2hh,
    const float* __restrict__ W1ho, const float* __restrict__ b1ho,
    const float* __restrict__ W2ho, const float* __restrict__ b2ho,
    float* __restrict__ out)
{
    extern __shared__ __align__(16) char smem[];
    float* sW1hh = (float*)(smem + OFF_W1HH);
    float* sW1ho = (float*)(smem + OFF_W1HO);
    float* sW2hh = (float*)(smem + OFF_W2HH);
    float* sW2ho = (float*)(smem + OFF_W2HO);
    float* sb1hh = (float*)(smem + OFF_B1HH);
    float* sb1ho = (float*)(smem + OFF_B1HO);
    float* sb2hh = (float*)(smem + OFF_B2HH);
    u64*   hbuf  = (u64*)  (smem + OFF_HBUF);   // packed h pairs
    u64*   sst   = (u64*)  (smem + OFF_SST);    // packed sigmoid(z_hh) pairs
    float* obuf  = (float*)(smem + OFF_OBUF);   // ho partial dots (ch 0..2)

    const int tid = threadIdx.x;
    for (int i = tid; i < 33 * FF; i += THREADS) { sW1hh[i] = W1hh[i]; sW1ho[i] = W1ho[i]; }
    for (int i = tid; i < FF * HIDDEN; i += THREADS) sW2hh[i] = W2hh[i];
    if (tid < FF) { sW2ho[tid] = W2ho[tid]; sb1hh[tid] = b1hh[tid]; sb1ho[tid] = b1ho[tid]; }
    if (tid < HIDDEN) sb2hh[tid] = b2hh[tid];
    for (int i = tid; i < 16 * EPB; i += THREADS) hbuf[i] = 0ull;   // h0 = 0
    const float bias_o = b2ho[0];
    __syncthreads();

    const int lane = tid & 31;
    const int wid  = tid >> 5;          // 0..7
    const int role = wid >> 2;          // 0 = hh, 1 = ho
    const int ch   = wid & 3;           // column group: j-pairs [5ch, 5ch+5)

    // 4 elements per thread: in-block slots lane, lane+32, lane+64, lane+96
    const size_t ebase = (size_t)blockIdx.x * EPB;
    const float* __restrict__ ip[4];
    float* __restrict__ op[4];
    #pragma unroll
    for (int k = 0; k < 4; k++) {
        ip[k] = inp + (ebase + lane + 32 * k) * TSTEPS;
        op[k] = out + (ebase + lane + 32 * k) * TSTEPS;
    }

    const float* __restrict__ W1 = role ? sW1ho : sW1hh;   // one loop body, role-selected
    const u64*  __restrict__ B1  = (const u64*)(role ? sb1ho : sb1hh) + ch * 5;
    const bool is_comb = (role == 1) && (ch == 3);

    float u[4];
    #pragma unroll
    for (int k = 0; k < 4; k++) u[k] = ip[k][0];

    #pragma unroll 1
    for (int t = 0; t < TSTEPS; t++) {
        float un[4];
        #pragma unroll
        for (int k = 0; k < 4; k++) un[k] = ip[k][(t + 1) & (TSTEPS - 1)];

        // ===== phase A: layer 1, 5 j-pairs, 4 elements =====
        u64 z[4][5];
        #pragma unroll
        for (int jp = 0; jp < 5; jp++) {
            u64 b = B1[jp];
            #pragma unroll
            for (int k = 0; k < 4; k++) z[k][jp] = b;
        }

        #pragma unroll 1
        for (int p = 0; p < 16; p++) {
            u64 cd0[4], cd1[4];
            #pragma unroll
            for (int k = 0; k < 4; k++) {
                float a, b; upk(hbuf[p * EPB + lane + 32 * k], a, b);
                cd0[k] = pk(a, a); cd1[k] = pk(b, b);
            }
            const u64* w0 = (const u64*)(W1 + (2 * p) * FF) + ch * 5;
            #pragma unroll
            for (int jp = 0; jp < 5; jp++) {
                u64 W = w0[jp];
                #pragma unroll
                for (int k = 0; k < 4; k++) z[k][jp] = f2fma(cd0[k], W, z[k][jp]);
            }
            const u64* w1 = (const u64*)(W1 + (2 * p + 1) * FF) + ch * 5;
            #pragma unroll
            for (int jp = 0; jp < 5; jp++) {
                u64 W = w1[jp];
                #pragma unroll
                for (int k = 0; k < 4; k++) z[k][jp] = f2fma(cd1[k], W, z[k][jp]);
            }
        }
        {   // input row 32
            u64 cu[4];
            #pragma unroll
            for (int k = 0; k < 4; k++) cu[k] = pk(u[k], u[k]);
            const u64* w = (const u64*)(W1 + 32 * FF) + ch * 5;
            #pragma unroll
            for (int jp = 0; jp < 5; jp++) {
                u64 W = w[jp];
                #pragma unroll
                for (int k = 0; k < 4; k++) z[k][jp] = f2fma(cu[k], W, z[k][jp]);
            }
        }

        float part[4] = {0.f, 0.f, 0.f, 0.f};
        if (role == 0) {
            // sigmoid -> sst pairs [5ch, 5ch+5)
            #pragma unroll
            for (int jp = 0; jp < 5; jp++) {
                #pragma unroll
                for (int k = 0; k < 4; k++) {
                    float a, b; upk(z[k][jp], a, b);
                    sst[(ch * 5 + jp) * EPB + lane + 32 * k] = pk(sigm(a), sigm(b));
                }
            }
        } else {
            // partial output dot over this warp's 5 pairs
            u64 acc[4] = {0ull, 0ull, 0ull, 0ull};
            const u64* wo = (const u64*)sW2ho + ch * 5;
            #pragma unroll
            for (int jp = 0; jp < 5; jp++) {
                u64 W = wo[jp];
                #pragma unroll
                for (int k = 0; k < 4; k++) {
                    float a, b; upk(z[k][jp], a, b);
                    acc[k] = f2fma(pk(sigm(a), sigm(b)), W, acc[k]);
                }
            }
            #pragma unroll
            for (int k = 0; k < 4; k++) {
                float a, b; upk(acc[k], a, b);
                part[k] = a + b;
            }
            if (ch < 3) {
                #pragma unroll
                for (int k = 0; k < 4; k++) obuf[ch * EPB + lane + 32 * k] = part[k];
            }
        }

        __syncthreads();   // sst/obuf published; all h reads complete

        // combiner writes out[t] (uses h_{t-1}: matches reference scan order)
        if (is_comb) {
            #pragma unroll
            for (int k = 0; k < 4; k++) {
                int ei = lane + 32 * k;
                op[k][t] = obuf[ei] + obuf[EPB + ei] + obuf[2 * EPB + ei]
                         + part[k] + bias_o;
            }
        }

        // ===== phase C: layer 2, pairs [2*wid, 2*wid+2), 4 elements =====
        {
            u64 hn[4][2];
            const u64* b2 = (const u64*)sb2hh + 2 * wid;
            #pragma unroll
            for (int q = 0; q < 2; q++) {
                u64 b = b2[q];
                #pragma unroll
                for (int k = 0; k < 4; k++) hn[k][q] = b;
            }
            #pragma unroll 1
            for (int jq = 0; jq < 20; jq++) {
                u64 p0[4], p1[4];
                #pragma unroll
                for (int k = 0; k < 4; k++) {
                    float s0, s1; upk(sst[jq * EPB + lane + 32 * k], s0, s1);
                    p0[k] = pk(s0, s0); p1[k] = pk(s1, s1);
                }
                const u64* w0 = (const u64*)(sW2hh + (2 * jq) * HIDDEN) + 2 * wid;
                #pragma unroll
                for (int q = 0; q < 2; q++) {
                    u64 W = w0[q];
                    #pragma unroll
                    for (int k = 0; k < 4; k++) hn[k][q] = f2fma(p0[k], W, hn[k][q]);
                }
                const u64* w1 = (const u64*)(sW2hh + (2 * jq + 1) * HIDDEN) + 2 * wid;
                #pragma unroll
                for (int q = 0; q < 2; q++) {
                    u64 W = w1[q];
                    #pragma unroll
                    for (int k = 0; k < 4; k++) hn[k][q] = f2fma(p1[k], W, hn[k][q]);
                }
            }
            #pragma unroll
            for (int q = 0; q < 2; q++)
                #pragma unroll
                for (int k = 0; k < 4; k++)
                    hbuf[(2 * wid + q) * EPB + lane + 32 * k] = hn[k][q];
        }

        __syncthreads();   // h_t complete; sst/obuf reusable next step

        #pragma unroll
        for (int k = 0; k < 4; k++) u[k] = un[k];
    }
}

extern "C" void kernel_launch(void* const* d_in, const int* in_sizes, int n_in,
                              void* d_out, int out_size) {
    const float* inp  = (const float*)d_in[0];
    const float* W1hh = (const float*)d_in[1];
    const float* b1hh = (const float*)d_in[2];
    const float* W2hh = (const float*)d_in[3];
    const float* b2hh = (const float*)d_in[4];
    const float* W1ho = (const float*)d_in[5];
    const float* b1ho = (const float*)d_in[6];
    const float* W2ho = (const float*)d_in[7];
    const float* b2ho = (const float*)d_in[8];
    float* out = (float*)d_out;

    // Idempotent, capture-safe.
    cudaFuncSetAttribute(rnn_e4_kernel,
                         cudaFuncAttributeMaxDynamicSharedMemorySize, SMEM_TOTAL);

    dim3 grid(BATCH / EPB);   // 128 blocks x 256 threads: 8 warps on each SM
    dim3 block(THREADS);
    rnn_e4_kernel<<<grid, block, SMEM_TOTAL>>>(inp, W1hh, b1hh, W2hh, b2hh,
                                               W1ho, b1ho, W2ho, b2ho, out);
}

// round 11
// speedup vs baseline: 1.5928x; 1.5928x over previous
#include <cuda_runtime.h>

#define HIDDEN 32
#define FF 40
#define TSTEPS 512
#define BATCH 16384
#define EPB 128           /* elements per block; each thread handles 4 */
#define THREADS 256       /* 8 warps x 5 column-pairs each = 40 pairs = 80 cols */

typedef unsigned long long u64;

__device__ __forceinline__ u64 pk(float a, float b) {
    u64 r; asm("mov.b64 %0,{%1,%2};" : "=l"(r) : "f"(a), "f"(b)); return r;
}
__device__ __forceinline__ void upk(u64 v, float& a, float& b) {
    asm("mov.b64 {%0,%1},%2;" : "=f"(a), "=f"(b) : "l"(v));
}
__device__ __forceinline__ u64 f2fma(u64 a, u64 b, u64 c) {
    u64 d; asm("fma.rn.f32x2 %0,%1,%2,%3;" : "=l"(d) : "l"(a), "l"(b), "l"(c)); return d;
}
// sigmoid via ex2/rcp approx (~1e-6 rel; proven across rounds)
__device__ __forceinline__ float sigm(float x) {
    float e, r;
    asm("ex2.approx.ftz.f32 %0,%1;" : "=f"(e) : "f"(x * -1.4426950408889634f));
    asm("rcp.approx.ftz.f32 %0,%1;" : "=f"(r) : "f"(1.0f + e));
    return r;
}

// Dynamic smem layout (bytes; every u64 region 8B-aligned)
#define OFF_WF   0            /* fused Wf[40][80] f32 = 12800           */
#define OFF_U    12800        /* u-row  [80] f32                        */
#define OFF_BF   13120        /* fused bias (recurrent) [80]            */
#define OFF_B0   13440        /* plain layer-1 bias (t=0) [80]          */
#define OFF_W2HO 13760        /* W2ho [40]                              */
#define OFF_SBUF 13920        /* u64[2][20*EPB] = 40960                 */
#define OFF_OBUF 54880        /* f32[2][4*EPB]  = 4096                  */
#define SMEM_TOTAL 58976

__global__ void __launch_bounds__(THREADS, 1) rnn_fused_kernel(
    const float* __restrict__ inp,
    const float* __restrict__ W1hh, const float* __restrict__ b1hh,
    const float* __restrict__ W2hh, const float* __restrict__ b2hh,
    const float* __restrict__ W1ho, const float* __restrict__ b1ho,
    const float* __restrict__ W2ho, const float* __restrict__ b2ho,
    float* __restrict__ out)
{
    extern __shared__ __align__(16) char smem[];
    float* sWf   = (float*)(smem + OFF_WF);    // [k<40][j<80]; j<40 hh, j>=40 ho
    float* sU    = (float*)(smem + OFF_U);
    float* sBf   = (float*)(smem + OFF_BF);
    float* sB0   = (float*)(smem + OFF_B0);
    float* sW2ho = (float*)(smem + OFF_W2HO);
    u64*   sbuf  = (u64*)  (smem + OFF_SBUF);  // s = sigmoid(z_hh), 20 pairs, x2 buffers
    float* obuf  = (float*)(smem + OFF_OBUF);  // 4 output partials, x2 buffers

    const int tid = threadIdx.x;

    // ---- init: fused weights Wf[k][j] = sum_i W2hh[k][i] * W1x[i][jcol] ----
    for (int idx = tid; idx < 40 * 80; idx += THREADS) {
        int k = idx / 80, j = idx % 80;
        const float* W1p = (j < 40) ? (W1hh + j) : (W1ho + (j - 40));  // stride 40 over i
        const float* W2p = W2hh + k * HIDDEN;
        float acc = 0.0f;
        #pragma unroll
        for (int i = 0; i < HIDDEN; i++) acc += W2p[i] * W1p[i * FF];
        sWf[idx] = acc;
    }
    // ---- u-row, biases ----
    for (int j = tid; j < 80; j += THREADS) {
        const float* W1p = (j < 40) ? (W1hh + j) : (W1ho + (j - 40));
        float b1 = (j < 40) ? b1hh[j] : b1ho[j - 40];
        float acc = 0.0f;
        #pragma unroll
        for (int i = 0; i < HIDDEN; i++) acc += b2hh[i] * W1p[i * FF];
        sB0[j] = b1;              // t=0: h0 = 0 exactly -> plain bias
        sBf[j] = b1 + acc;        // t>0: bias absorbs b2hh @ W1[0:32]
        sU[j]  = W1p[32 * FF];    // input row W1[32][jcol]
    }
    for (int j = tid; j < FF; j += THREADS) sW2ho[j] = W2ho[j];
    const float bias_o = b2ho[0];
    __syncthreads();

    const int lane = tid & 31;
    const int wid  = tid >> 5;          // 0..7; pairs [5*wid, 5*wid+5)
    const bool is_hh = (wid < 4);       // cols 0..39 -> s state; 40..79 -> output head
    const int JB = 5 * wid;             // global column-pair base

    const size_t ebase = (size_t)blockIdx.x * EPB;
    const float* __restrict__ ip[4];
    float* __restrict__ op[4];
    #pragma unroll
    for (int k = 0; k < 4; k++) {
        ip[k] = inp + (ebase + lane + 32 * k) * TSTEPS;
        op[k] = out + (ebase + lane + 32 * k) * TSTEPS;
    }

    const u64* U64  = (const u64*)sU  + JB;
    const u64* Bf64 = (const u64*)sBf + JB;
    const u64* Wo64 = (const u64*)sW2ho + (JB - 20);   // valid for ho warps only

    // ---- t = 0: z = u0 * Urow + b1 (h0 = 0) ----
    u64 z[4][5];
    {
        const u64* B0p = (const u64*)sB0 + JB;
        float u0[4];
        #pragma unroll
        for (int k = 0; k < 4; k++) u0[k] = ip[k][0];
        #pragma unroll
        for (int q = 0; q < 5; q++) {
            u64 Uq = U64[q], Bq = B0p[q];
            #pragma unroll
            for (int k = 0; k < 4; k++) z[k][q] = f2fma(pk(u0[k], u0[k]), Uq, z[k][q] = Bq);
        }
    }

    #pragma unroll 1
    for (int t = 0; t < TSTEPS; t++) {
        const int par = t & 1;
        float un[4];
        #pragma unroll
        for (int k = 0; k < 4; k++) un[k] = ip[k][(t + 1) & (TSTEPS - 1)];

        // ===== phase 1: consume z[t] =====
        if (is_hh) {
            // s = sigmoid(z_hh) -> sbuf[par], pairs [JB, JB+5)
            u64* sb = sbuf + par * (20 * EPB);
            #pragma unroll
            for (int q = 0; q < 5; q++) {
                #pragma unroll
                for (int k = 0; k < 4; k++) {
                    float a, b; upk(z[k][q], a, b);
                    sb[(JB + q) * EPB + lane + 32 * k] = pk(sigm(a), sigm(b));
                }
            }
        } else {
            // partial out dot: sigmoid(z_ho) . W2ho[slice] -> obuf[par][wid-4]
            u64 acc[4] = {0ull, 0ull, 0ull, 0ull};
            #pragma unroll
            for (int q = 0; q < 5; q++) {
                u64 W = Wo64[q];
                #pragma unroll
                for (int k = 0; k < 4; k++) {
                    float a, b; upk(z[k][q], a, b);
                    acc[k] = f2fma(pk(sigm(a), sigm(b)), W, acc[k]);
                }
            }
            float* ob = obuf + par * (4 * EPB) + (wid - 4) * EPB;
            #pragma unroll
            for (int k = 0; k < 4; k++) {
                float a, b; upk(acc[k], a, b);
                ob[lane + 32 * k] = a + b;
            }
        }

        __syncthreads();   // s + output partials published

        // warp 0 combines the 4 partials and writes out[t]
        if (wid == 0) {
            const float* ob = obuf + par * (4 * EPB);
            #pragma unroll
            for (int k = 0; k < 4; k++) {
                int ei = lane + 32 * k;
                op[k][t] = ob[ei] + ob[EPB + ei] + ob[2 * EPB + ei] + ob[3 * EPB + ei]
                         + bias_o;
            }
        }

        // ===== phase 2: GEMV -> z[t+1] = s @ Wf + u_{t+1}*U + Bf =====
        #pragma unroll
        for (int q = 0; q < 5; q++) {
            u64 Uq = U64[q], Bq = Bf64[q];
            #pragma unroll
            for (int k = 0; k < 4; k++) z[k][q] = f2fma(pk(un[k], un[k]), Uq, Bq);
        }
        {
            const u64* sb = sbuf + par * (20 * EPB);
            #pragma unroll 2
            for (int kp = 0; kp < 20; kp++) {
                u64 p0[4], p1[4];
                #pragma unroll
                for (int k = 0; k < 4; k++) {
                    float s0, s1; upk(sb[kp * EPB + lane + 32 * k], s0, s1);
                    p0[k] = pk(s0, s0); p1[k] = pk(s1, s1);
                }
                const u64* w0 = (const u64*)(sWf + (2 * kp) * 80) + JB;
                #pragma unroll
                for (int q = 0; q < 5; q++) {
                    u64 W = w0[q];
                    #pragma unroll
                    for (int k = 0; k < 4; k++) z[k][q] = f2fma(p0[k], W, z[k][q]);
                }
                const u64* w1 = (const u64*)(sWf + (2 * kp + 1) * 80) + JB;
                #pragma unroll
                for (int q = 0; q < 5; q++) {
                    u64 W = w1[q];
                    #pragma unroll
                    for (int k = 0; k < 4; k++) z[k][q] = f2fma(p1[k], W, z[k][q]);
                }
            }
        }
        // no second barrier needed: next iteration writes the OTHER s/obuf
        // parity, and >=1-iteration skew is impossible across the single
        // per-step barrier.
    }
}

extern "C" void kernel_launch(void* const* d_in, const int* in_sizes, int n_in,
                              void* d_out, int out_size) {
    const float* inp  = (const float*)d_in[0];
    const float* W1hh = (const float*)d_in[1];
    const float* b1hh = (const float*)d_in[2];
    const float* W2hh = (const float*)d_in[3];
    const float* b2hh = (const float*)d_in[4];
    const float* W1ho = (const float*)d_in[5];
    const float* b1ho = (const float*)d_in[6];
    const float* W2ho = (const float*)d_in[7];
    const float* b2ho = (const float*)d_in[8];
    float* out = (float*)d_out;

    // Idempotent, capture-safe.
    cudaFuncSetAttribute(rnn_fused_kernel,
                         cudaFuncAttributeMaxDynamicSharedMemorySize, SMEM_TOTAL);

    dim3 grid(BATCH / EPB);   // 128 blocks x 256 threads
    dim3 block(THREADS);
    rnn_fused_kernel<<<grid, block, SMEM_TOTAL>>>(inp, W1hh, b1hh, W2hh, b2hh,
                                                  W1ho, b1ho, W2ho, b2ho, out);
}